// round 7
// baseline (speedup 1.0000x reference)
#include <cuda_runtime.h>

// Problem constants
#define N_    64
#define C_    64
#define T_    300
#define V_    25
#define IC_   16
#define NS_   3

typedef unsigned long long ull;

__device__ __forceinline__ ull dup2(float v) {
    ull r; asm("mov.b64 %0, {%1, %1};" : "=l"(r) : "f"(v)); return r;
}
__device__ __forceinline__ void fma2(ull& acc, ull a, ull b) {
    asm("fma.rn.f32x2 %0, %1, %2, %0;" : "+l"(acc) : "l"(a), "l"(b));
}
__device__ __forceinline__ void unpack2(ull v, float& lo, float& hi) {
    asm("mov.b64 {%0, %1}, %2;" : "=f"(lo), "=f"(hi) : "l"(v));
}

// Intermediate M buffer: M[s][n][t][v]
__device__ float g_M[NS_ * N_ * T_ * V_];

// ======================= Kernel A: attention -> M =======================
#define TCA   12
#define COLSA 300          // TCA * V_
#define NTA   300
#define GRIDA (N_ * (T_ / TCA))   // 1600

struct SmemA {
    float WabT[NS_][64][32];    // [s][c][r]  r<16: a_w, r>=16: b_w   24576 B
    float xs[64][COLSA];        // 76800 B (row 1200B, 16B-div)
    float CaCb[32][TCA * 28];   // 43008 B (row 1344B, 16B-div)
    float Pm[TCA][25][26];      // 31200 B
    float colA[NS_][32];
    float absh[NS_][32];
};

__global__ void __launch_bounds__(NTA, 1)
tsagc_attn_kernel(const float* __restrict__ x,
                  const float* __restrict__ A,
                  const float* __restrict__ GA,
                  const float* __restrict__ a_w,
                  const float* __restrict__ a_b,
                  const float* __restrict__ b_w,
                  const float* __restrict__ b_b)
{
    extern __shared__ float smem_raw[];
    SmemA& sm = *reinterpret_cast<SmemA*>(smem_raw);
    const int tid = threadIdx.x;

    // ---- stage weights ----
    for (int idx = tid; idx < NS_ * IC_ * 64; idx += NTA) {
        int c  = idx & 63;
        int ic = (idx >> 6) & 15;
        int s  = idx >> 10;
        sm.WabT[s][c][ic]      = a_w[idx];
        sm.WabT[s][c][16 + ic] = b_w[idx];
    }
    for (int idx = tid; idx < NS_ * IC_; idx += NTA) {
        int s = idx / IC_, ic = idx % IC_;
        sm.absh[s][ic]      = a_b[idx];
        sm.absh[s][16 + ic] = b_b[idx];
    }
    for (int idx = tid; idx < NS_ * V_; idx += NTA) {
        int s = idx / V_, v = idx % V_;
        float acc = 0.f;
        #pragma unroll 5
        for (int a = 0; a < V_; a++) {
            int off = (s * V_ + a) * V_ + v;
            acc += A[off] + GA[off];
        }
        sm.colA[s][v] = acc;
    }
    // zero CaCb pad columns v=25..27
    for (int idx = tid; idx < 32 * TCA * 3; idx += NTA) {
        int r = idx / (TCA * 3);
        int q = idx % (TCA * 3);
        sm.CaCb[r][(q / 3) * 28 + 25 + (q % 3)] = 0.f;
    }

    // ---- load x chunk (t0 multiple of 12 -> 16B aligned) ----
    const int n  = blockIdx.x / (T_ / TCA);
    const int t0 = (blockIdx.x % (T_ / TCA)) * TCA;
    const float* xg = x + (n * 64 * T_ + t0) * V_;
    for (int idx = tid; idx < 64 * (COLSA / 4); idx += NTA) {
        int c = idx / (COLSA / 4), q = idx % (COLSA / 4);
        float4 val = *reinterpret_cast<const float4*>(xg + c * (T_ * V_) + q * 4);
        *reinterpret_cast<float4*>(&sm.xs[c][q * 4]) = val;
    }
    __syncthreads();

    // phase-1 mapping: 4 row-groups (8 rows each) x 75 col-groups (4 cols)
    const int rg   = tid / 75;     // 0..3
    const int cg   = tid % 75;     // 0..74
    const int col0 = cg * 4;
    const int r0   = rg * 8;

    int tcv[4], vv[4];
    #pragma unroll
    for (int j = 0; j < 4; j++) {
        int col = col0 + j;
        tcv[j] = col / 25;
        vv[j]  = col - tcv[j] * 25;
    }

    for (int s = 0; s < NS_; s++) {
        // ---- Phase 1: CaCb = Wab[s] @ xs (8 rows x 4 cols, pairs on rows) ----
        {
            ull acc2[4][4];   // [row-pair][col]
            #pragma unroll
            for (int k = 0; k < 4; k++)
                #pragma unroll
                for (int j = 0; j < 4; j++) acc2[k][j] = 0ull;
            #pragma unroll 2
            for (int c = 0; c < 64; c++) {
                ulonglong2 wp0 = *reinterpret_cast<const ulonglong2*>(&sm.WabT[s][c][r0]);
                ulonglong2 wp1 = *reinterpret_cast<const ulonglong2*>(&sm.WabT[s][c][r0 + 4]);
                float4 xv = *reinterpret_cast<const float4*>(&sm.xs[c][col0]);
                ull xd[4] = {dup2(xv.x), dup2(xv.y), dup2(xv.z), dup2(xv.w)};
                #pragma unroll
                for (int j = 0; j < 4; j++) {
                    fma2(acc2[0][j], wp0.x, xd[j]);
                    fma2(acc2[1][j], wp0.y, xd[j]);
                    fma2(acc2[2][j], wp1.x, xd[j]);
                    fma2(acc2[3][j], wp1.y, xd[j]);
                }
            }
            #pragma unroll
            for (int k = 0; k < 4; k++) {
                float bA = sm.absh[s][r0 + 2 * k];
                float bB = sm.absh[s][r0 + 2 * k + 1];
                #pragma unroll
                for (int j = 0; j < 4; j++) {
                    float lo, hi;
                    unpack2(acc2[k][j], lo, hi);
                    int off = tcv[j] * 28 + vv[j];
                    sm.CaCb[r0 + 2 * k][off]     = lo + bA;
                    sm.CaCb[r0 + 2 * k + 1][off] = hi + bB;
                }
            }
        }
        __syncthreads();

        // ---- Phase 2a: logits + softmax, 2 rows per thread (156 threads) ----
        if (tid < 156) {
            const int tc = tid / 13, a0 = tid % 13;
            const int a1 = a0 + 13;
            const bool has2 = (a1 < 25);
            const int tcBase = tc * 28;
            ull lA[13], lB[13];
            #pragma unroll
            for (int p = 0; p < 13; p++) { lA[p] = 0ull; lB[p] = 0ull; }
            #pragma unroll 4
            for (int ic = 0; ic < 16; ic++) {
                ull cad0 = dup2(sm.CaCb[ic][tcBase + a0]);
                ull cad1 = has2 ? dup2(sm.CaCb[ic][tcBase + a1]) : 0ull;
                const ulonglong2* cb =
                    reinterpret_cast<const ulonglong2*>(&sm.CaCb[16 + ic][tcBase]);
                #pragma unroll
                for (int q = 0; q < 6; q++) {
                    ulonglong2 cv = cb[q];
                    fma2(lA[q * 2],     cad0, cv.x);
                    fma2(lA[q * 2 + 1], cad0, cv.y);
                    fma2(lB[q * 2],     cad1, cv.x);
                    fma2(lB[q * 2 + 1], cad1, cv.y);
                }
                ulonglong2 cv6 = cb[6];
                fma2(lA[12], cad0, cv6.x);
                fma2(lB[12], cad1, cv6.x);
            }
            {
                float l[26];
                #pragma unroll
                for (int p = 0; p < 13; p++) unpack2(lA[p], l[2 * p], l[2 * p + 1]);
                float mx = -1e30f;
                #pragma unroll
                for (int b = 0; b < 25; b++) { l[b] *= 0.0625f; mx = fmaxf(mx, l[b]); }
                float ssum = 0.f;
                #pragma unroll
                for (int b = 0; b < 25; b++) { float e = __expf(l[b] - mx); ssum += e; l[b] = e; }
                float inv = 1.f / ssum;
                float* pr = sm.Pm[tc][a0];
                #pragma unroll
                for (int b = 0; b < 25; b++) pr[b] = l[b] * inv;
            }
            if (has2) {
                float l[26];
                #pragma unroll
                for (int p = 0; p < 13; p++) unpack2(lB[p], l[2 * p], l[2 * p + 1]);
                float mx = -1e30f;
                #pragma unroll
                for (int b = 0; b < 25; b++) { l[b] *= 0.0625f; mx = fmaxf(mx, l[b]); }
                float ssum = 0.f;
                #pragma unroll
                for (int b = 0; b < 25; b++) { float e = __expf(l[b] - mx); ssum += e; l[b] = e; }
                float inv = 1.f / ssum;
                float* pr = sm.Pm[tc][a1];
                #pragma unroll
                for (int b = 0; b < 25; b++) pr[b] = l[b] * inv;
            }
        }
        __syncthreads();

        // ---- Phase 2b: column sums -> g_M (300 threads, perfect fit) ----
        {
            const int tc = tid / 25, b = tid % 25;
            float msum = sm.colA[s][b];
            #pragma unroll 5
            for (int a = 0; a < 25; a++) msum += sm.Pm[tc][a][b];
            g_M[((s * N_ + n) * T_ + t0 + tc) * V_ + b] = msum;
        }
        __syncthreads();
    }
}

// ======================= Kernel B: output GEMM =======================
#define TCB   12
#define COLSB 300          // TCB * V_
#define NTB   300
#define GRIDB (N_ * (T_ / TCB))   // 1600

struct SmemB {
    float GT[NS_][64][64];     // [s][c][o]   49152 B
    float xs[64][COLSB];       // 76800 B
    float Msm[NS_][COLSB];     // 3600 B
    float scArr[64];
    float shArr[64];
};

__global__ void __launch_bounds__(NTB, 1)
tsagc_out_kernel(const float* __restrict__ x,
                 const float* __restrict__ g_w,
                 const float* __restrict__ g_b,
                 const float* __restrict__ bn_gamma,
                 const float* __restrict__ bn_beta,
                 const float* __restrict__ bn_mean,
                 const float* __restrict__ bn_var,
                 float* __restrict__ out)
{
    extern __shared__ float smem_raw[];
    SmemB& sm = *reinterpret_cast<SmemB*>(smem_raw);
    const int tid = threadIdx.x;

    // ---- stage GT (g_w transposed) ----
    for (int idx = tid; idx < NS_ * 64 * 64; idx += NTB) {
        int c = idx & 63;
        int o = (idx >> 6) & 63;
        int s = idx >> 12;
        sm.GT[s][c][o] = g_w[idx];
    }
    if (tid < 64) {
        float inv = rsqrtf(bn_var[tid] + 1e-5f);
        float scv = bn_gamma[tid] * inv;
        sm.scArr[tid] = scv;
        float cb = g_b[tid] + g_b[64 + tid] + g_b[128 + tid];
        sm.shArr[tid] = (cb - bn_mean[tid]) * scv + bn_beta[tid];
    }

    const int n  = blockIdx.x / (T_ / TCB);
    const int t0 = (blockIdx.x % (T_ / TCB)) * TCB;

    // ---- load x chunk (float4, t0*25 mult of 300) ----
    const float* xg = x + (n * 64 * T_ + t0) * V_;
    for (int idx = tid; idx < 64 * (COLSB / 4); idx += NTB) {
        int c = idx / (COLSB / 4), q = idx % (COLSB / 4);
        float4 val = *reinterpret_cast<const float4*>(xg + c * (T_ * V_) + q * 4);
        *reinterpret_cast<float4*>(&sm.xs[c][q * 4]) = val;
    }
    // ---- load M chunk ----
    for (int idx = tid; idx < NS_ * (COLSB / 4); idx += NTB) {
        int s = idx / (COLSB / 4), q = idx % (COLSB / 4);
        float4 val = *reinterpret_cast<const float4*>(
            &g_M[(s * N_ + n) * (T_ * V_) + t0 * V_ + q * 4]);
        *reinterpret_cast<float4*>(&sm.Msm[s][q * 4]) = val;
    }
    __syncthreads();

    // ---- mainloop: 16 rows (8 o-pairs) x 4 cols per thread ----
    const int rg   = tid / 75;     // 0..3 -> o0 = rg*16
    const int cg   = tid % 75;     // 0..74
    const int col0 = cg * 4;
    const int o0   = rg * 16;

    float ms[NS_][4];
    #pragma unroll
    for (int s = 0; s < NS_; s++)
        #pragma unroll
        for (int j = 0; j < 4; j++) ms[s][j] = sm.Msm[s][col0 + j];

    ull acc2[8][4];   // [o-pair][col]
    #pragma unroll
    for (int k = 0; k < 8; k++)
        #pragma unroll
        for (int j = 0; j < 4; j++) acc2[k][j] = 0ull;

    #pragma unroll 2
    for (int c = 0; c < 64; c++) {
        float4 xv = *reinterpret_cast<const float4*>(&sm.xs[c][col0]);
        float xa[4] = {xv.x, xv.y, xv.z, xv.w};
        #pragma unroll
        for (int s = 0; s < NS_; s++) {
            const ulonglong2* gp =
                reinterpret_cast<const ulonglong2*>(&sm.GT[s][c][o0]);
            ulonglong2 g01 = gp[0];
            ulonglong2 g23 = gp[1];
            ulonglong2 g45 = gp[2];
            ulonglong2 g67 = gp[3];
            ull xm[4];
            #pragma unroll
            for (int j = 0; j < 4; j++) xm[j] = dup2(xa[j] * ms[s][j]);
            #pragma unroll
            for (int j = 0; j < 4; j++) {
                fma2(acc2[0][j], g01.x, xm[j]);
                fma2(acc2[1][j], g01.y, xm[j]);
                fma2(acc2[2][j], g23.x, xm[j]);
                fma2(acc2[3][j], g23.y, xm[j]);
                fma2(acc2[4][j], g45.x, xm[j]);
                fma2(acc2[5][j], g45.y, xm[j]);
                fma2(acc2[6][j], g67.x, xm[j]);
                fma2(acc2[7][j], g67.y, xm[j]);
            }
        }
    }

    // ---- epilogue: BN + residual + ReLU, float4 stores ----
    #pragma unroll
    for (int k = 0; k < 8; k++) {
        int oa = o0 + 2 * k;
        int ob = oa + 1;
        float scA = sm.scArr[oa], shA = sm.shArr[oa];
        float scB = sm.scArr[ob], shB = sm.shArr[ob];
        float ra[4], rb[4];
        #pragma unroll
        for (int j = 0; j < 4; j++) unpack2(acc2[k][j], ra[j], rb[j]);
        float4 xrA = *reinterpret_cast<const float4*>(&sm.xs[oa][col0]);
        float4 xrB = *reinterpret_cast<const float4*>(&sm.xs[ob][col0]);
        float4 resA, resB;
        resA.x = fmaxf(ra[0] * scA + shA + xrA.x, 0.f);
        resA.y = fmaxf(ra[1] * scA + shA + xrA.y, 0.f);
        resA.z = fmaxf(ra[2] * scA + shA + xrA.z, 0.f);
        resA.w = fmaxf(ra[3] * scA + shA + xrA.w, 0.f);
        resB.x = fmaxf(rb[0] * scB + shB + xrB.x, 0.f);
        resB.y = fmaxf(rb[1] * scB + shB + xrB.y, 0.f);
        resB.z = fmaxf(rb[2] * scB + shB + xrB.z, 0.f);
        resB.w = fmaxf(rb[3] * scB + shB + xrB.w, 0.f);
        float* opA = out + (n * 64 + oa) * (T_ * V_) + t0 * V_ + col0;
        float* opB = out + (n * 64 + ob) * (T_ * V_) + t0 * V_ + col0;
        *reinterpret_cast<float4*>(opA) = resA;
        *reinterpret_cast<float4*>(opB) = resB;
    }
}

extern "C" void kernel_launch(void* const* d_in, const int* in_sizes, int n_in,
                              void* d_out, int out_size)
{
    const float* x        = (const float*)d_in[0];
    const float* A        = (const float*)d_in[1];
    const float* GA       = (const float*)d_in[2];
    const float* g_w      = (const float*)d_in[3];
    const float* g_b      = (const float*)d_in[4];
    const float* a_w      = (const float*)d_in[5];
    const float* a_b      = (const float*)d_in[6];
    const float* b_w      = (const float*)d_in[7];
    const float* b_b      = (const float*)d_in[8];
    const float* bn_gamma = (const float*)d_in[9];
    const float* bn_beta  = (const float*)d_in[10];
    const float* bn_mean  = (const float*)d_in[11];
    const float* bn_var   = (const float*)d_in[12];
    float* out = (float*)d_out;

    size_t smemA = sizeof(SmemA);
    size_t smemB = sizeof(SmemB);
    cudaFuncSetAttribute(tsagc_attn_kernel,
                         cudaFuncAttributeMaxDynamicSharedMemorySize, (int)smemA);
    cudaFuncSetAttribute(tsagc_out_kernel,
                         cudaFuncAttributeMaxDynamicSharedMemorySize, (int)smemB);

    tsagc_attn_kernel<<<GRIDA, NTA, smemA>>>(x, A, GA, a_w, a_b, b_w, b_b);
    tsagc_out_kernel<<<GRIDB, NTB, smemB>>>(x, g_w, g_b, bn_gamma, bn_beta,
                                            bn_mean, bn_var, out);
}

// round 8
// speedup vs baseline: 1.1636x; 1.1636x over previous
#include <cuda_runtime.h>

// Problem constants
#define N_    64
#define C_    64
#define T_    300
#define V_    25
#define IC_   16
#define NS_   3

typedef unsigned long long ull;

__device__ __forceinline__ ull dup2(float v) {
    ull r; asm("mov.b64 %0, {%1, %1};" : "=l"(r) : "f"(v)); return r;
}
__device__ __forceinline__ void fma2(ull& acc, ull a, ull b) {
    asm("fma.rn.f32x2 %0, %1, %2, %0;" : "+l"(acc) : "l"(a), "l"(b));
}
__device__ __forceinline__ void unpack2(ull v, float& lo, float& hi) {
    asm("mov.b64 {%0, %1}, %2;" : "=f"(lo), "=f"(hi) : "l"(v));
}

// Fast exp on the FMA pipe (no MUFU). |rel err| ~2e-6 for x <= 0.
__device__ __forceinline__ float fastexp(float x) {
    const float L2E = 1.4426950408889634f;
    x = fmaxf(x, -80.0f);
    float t = fmaf(x, L2E, 12582912.0f);      // 1.5*2^23 magic round
    float k = t - 12582912.0f;
    float f = fmaf(x, L2E, -k);               // f in [-0.5, 0.5]
    float p =              1.3333558146e-3f;
    p = fmaf(p, f, 9.6181291076e-3f);
    p = fmaf(p, f, 5.5504108664e-2f);
    p = fmaf(p, f, 2.4022650696e-1f);
    p = fmaf(p, f, 6.9314718056e-1f);
    p = fmaf(p, f, 1.0f);
    int ik = __float_as_int(t) - 0x4B400000;  // exact integer k
    float scale = __int_as_float((ik + 127) << 23);
    return p * scale;
}

// Intermediate M buffer: M[s][n][t][v]
__device__ float g_M[NS_ * N_ * T_ * V_];

// ======================= Kernel A: attention -> M =======================
#define TCA   4
#define COLSA 100
#define NTA   200
#define GRIDA (N_ * (T_ / TCA))   // 4800

struct SmemA {
    float WabT[NS_][64][32];        // 24576 B  [s][c][r] r<16:a_w r>=16:b_w
    float xs[64][COLSA];            // 25600 B
    float CaCb[NS_][32][TCA * 28];  // 43008 B  [s][r][tc*28+v]
    float Pm[TCA][25][26];          // 10400 B  (single-s, reused)
    float colA[NS_][32];
    float absh[NS_][32];
};

__global__ void __launch_bounds__(NTA, 2)
tsagc_attn_kernel(const float* __restrict__ x,
                  const float* __restrict__ A,
                  const float* __restrict__ GA,
                  const float* __restrict__ a_w,
                  const float* __restrict__ a_b,
                  const float* __restrict__ b_w,
                  const float* __restrict__ b_b)
{
    extern __shared__ float smem_raw[];
    SmemA& sm = *reinterpret_cast<SmemA*>(smem_raw);
    const int tid = threadIdx.x;

    // ---- stage weights / constants ----
    for (int idx = tid; idx < NS_ * IC_ * 64; idx += NTA) {
        int c  = idx & 63;
        int ic = (idx >> 6) & 15;
        int s  = idx >> 10;
        sm.WabT[s][c][ic]      = a_w[idx];
        sm.WabT[s][c][16 + ic] = b_w[idx];
    }
    for (int idx = tid; idx < NS_ * IC_; idx += NTA) {
        int s = idx / IC_, ic = idx % IC_;
        sm.absh[s][ic]      = a_b[idx];
        sm.absh[s][16 + ic] = b_b[idx];
    }
    for (int idx = tid; idx < NS_ * V_; idx += NTA) {
        int s = idx / V_, v = idx % V_;
        float acc = 0.f;
        #pragma unroll 5
        for (int a = 0; a < V_; a++) {
            int off = (s * V_ + a) * V_ + v;
            acc += A[off] + GA[off];
        }
        sm.colA[s][v] = acc;
    }
    // zero CaCb pad columns v=25..27 (all s)
    for (int idx = tid; idx < NS_ * 32 * TCA * 3; idx += NTA) {
        int s = idx / (32 * TCA * 3);
        int r = (idx / (TCA * 3)) % 32;
        int q = idx % (TCA * 3);
        sm.CaCb[s][r][(q / 3) * 28 + 25 + (q % 3)] = 0.f;
    }

    // ---- load x chunk ----
    const int n  = blockIdx.x / (T_ / TCA);
    const int t0 = (blockIdx.x % (T_ / TCA)) * TCA;
    const float* xg = x + (n * 64 * T_ + t0) * V_;
    for (int idx = tid; idx < 64 * (COLSA / 4); idx += NTA) {
        int c = idx / (COLSA / 4), q = idx % (COLSA / 4);
        float4 val = *reinterpret_cast<const float4*>(xg + c * (T_ * V_) + q * 4);
        *reinterpret_cast<float4*>(&sm.xs[c][q * 4]) = val;
    }
    __syncthreads();

    // ---- Phase 1 (fused over s): CaCb[s] = Wab[s] @ xs, 4x4 tiles ----
    {
        const int rg   = tid / 25;     // 0..7
        const int cg   = tid % 25;     // 0..24
        const int col0 = cg * 4;
        const int r0   = rg * 4;

        int tcv[4], vv[4];
        #pragma unroll
        for (int j = 0; j < 4; j++) {
            int col = col0 + j;
            tcv[j] = col / 25;
            vv[j]  = col - tcv[j] * 25;
        }

        ull acc2[NS_][2][4];   // [s][row-pair][col]
        #pragma unroll
        for (int s = 0; s < NS_; s++)
            #pragma unroll
            for (int k = 0; k < 2; k++)
                #pragma unroll
                for (int j = 0; j < 4; j++) acc2[s][k][j] = 0ull;

        #pragma unroll 2
        for (int c = 0; c < 64; c++) {
            float4 xv = *reinterpret_cast<const float4*>(&sm.xs[c][col0]);
            ull xd[4] = {dup2(xv.x), dup2(xv.y), dup2(xv.z), dup2(xv.w)};
            #pragma unroll
            for (int s = 0; s < NS_; s++) {
                ulonglong2 wp = *reinterpret_cast<const ulonglong2*>(&sm.WabT[s][c][r0]);
                #pragma unroll
                for (int j = 0; j < 4; j++) {
                    fma2(acc2[s][0][j], wp.x, xd[j]);
                    fma2(acc2[s][1][j], wp.y, xd[j]);
                }
            }
        }
        #pragma unroll
        for (int s = 0; s < NS_; s++) {
            #pragma unroll
            for (int k = 0; k < 2; k++) {
                float bA = sm.absh[s][r0 + 2 * k];
                float bB = sm.absh[s][r0 + 2 * k + 1];
                #pragma unroll
                for (int j = 0; j < 4; j++) {
                    float lo, hi;
                    unpack2(acc2[s][k][j], lo, hi);
                    int off = tcv[j] * 28 + vv[j];
                    sm.CaCb[s][r0 + 2 * k][off]     = lo + bA;
                    sm.CaCb[s][r0 + 2 * k + 1][off] = hi + bB;
                }
            }
        }
    }
    __syncthreads();

    // ---- Phases 2a/2b per subset ----
    for (int s = 0; s < NS_; s++) {
        // 2a: logits + softmax, 2 rows per thread (52 threads)
        if (tid < 52) {
            const int tc = tid / 13, a0 = tid % 13;
            const int a1 = a0 + 13;
            const bool has2 = (a0 < 12);
            const int tcBase = tc * 28;
            ull lA[13], lB[13];
            #pragma unroll
            for (int p = 0; p < 13; p++) { lA[p] = 0ull; lB[p] = 0ull; }
            #pragma unroll 4
            for (int ic = 0; ic < 16; ic++) {
                ull cad0 = dup2(sm.CaCb[s][ic][tcBase + a0]);
                ull cad1 = has2 ? dup2(sm.CaCb[s][ic][tcBase + a1]) : 0ull;
                const ulonglong2* cb =
                    reinterpret_cast<const ulonglong2*>(&sm.CaCb[s][16 + ic][tcBase]);
                #pragma unroll
                for (int q = 0; q < 6; q++) {
                    ulonglong2 cv = cb[q];
                    fma2(lA[q * 2],     cad0, cv.x);
                    fma2(lA[q * 2 + 1], cad0, cv.y);
                    fma2(lB[q * 2],     cad1, cv.x);
                    fma2(lB[q * 2 + 1], cad1, cv.y);
                }
                ulonglong2 cv6 = cb[6];
                fma2(lA[12], cad0, cv6.x);
                fma2(lB[12], cad1, cv6.x);
            }
            {
                float l[26];
                #pragma unroll
                for (int p = 0; p < 13; p++) unpack2(lA[p], l[2 * p], l[2 * p + 1]);
                float mx = -1e30f;
                #pragma unroll
                for (int b = 0; b < 25; b++) { l[b] *= 0.0625f; mx = fmaxf(mx, l[b]); }
                float ssum = 0.f;
                #pragma unroll
                for (int b = 0; b < 25; b++) { float e = fastexp(l[b] - mx); ssum += e; l[b] = e; }
                float inv = 1.f / ssum;
                float* pr = sm.Pm[tc][a0];
                #pragma unroll
                for (int b = 0; b < 25; b++) pr[b] = l[b] * inv;
            }
            if (has2) {
                float l[26];
                #pragma unroll
                for (int p = 0; p < 13; p++) unpack2(lB[p], l[2 * p], l[2 * p + 1]);
                float mx = -1e30f;
                #pragma unroll
                for (int b = 0; b < 25; b++) { l[b] *= 0.0625f; mx = fmaxf(mx, l[b]); }
                float ssum = 0.f;
                #pragma unroll
                for (int b = 0; b < 25; b++) { float e = fastexp(l[b] - mx); ssum += e; l[b] = e; }
                float inv = 1.f / ssum;
                float* pr = sm.Pm[tc][a1];
                #pragma unroll
                for (int b = 0; b < 25; b++) pr[b] = l[b] * inv;
            }
        }
        __syncthreads();

        // 2b: column sums -> g_M (100 threads)
        if (tid < 100) {
            const int tc = tid / 25, b = tid % 25;
            float msum = sm.colA[s][b];
            #pragma unroll 5
            for (int a = 0; a < 25; a++) msum += sm.Pm[tc][a][b];
            g_M[((s * N_ + n) * T_ + t0 + tc) * V_ + b] = msum;
        }
        __syncthreads();   // protect Pm before next-s overwrite
    }
}

// ======================= Kernel B: output GEMM (o-split) =======================
#define TCB   12
#define COLSB 300
#define NTB   300
#define GRIDB (N_ * (T_ / TCB) * 2)   // 3200

struct SmemB {
    float GTh[NS_][64][32];    // 24576 B  [s][c][o_local], o-half
    float xs[64][COLSB];       // 76800 B
    float Msm[NS_][COLSB];     // 3600 B
    float scArr[32];
    float shArr[32];
};

__global__ void __launch_bounds__(NTB, 2)
tsagc_out_kernel(const float* __restrict__ x,
                 const float* __restrict__ g_w,
                 const float* __restrict__ g_b,
                 const float* __restrict__ bn_gamma,
                 const float* __restrict__ bn_beta,
                 const float* __restrict__ bn_mean,
                 const float* __restrict__ bn_var,
                 float* __restrict__ out)
{
    extern __shared__ float smem_raw[];
    SmemB& sm = *reinterpret_cast<SmemB*>(smem_raw);
    const int tid = threadIdx.x;

    const int bid    = blockIdx.x;
    const int n      = bid / (2 * (T_ / TCB));
    const int rem    = bid % (2 * (T_ / TCB));
    const int t0     = (rem >> 1) * TCB;
    const int o_base = (rem & 1) * 32;

    // ---- stage GT half (transposed) ----
    for (int idx = tid; idx < NS_ * 64 * 32; idx += NTB) {
        int ol = idx & 31;
        int c  = (idx >> 5) & 63;
        int s  = idx >> 11;
        sm.GTh[s][c][ol] = g_w[(s * 64 + o_base + ol) * 64 + c];
    }
    if (tid < 32) {
        int o = o_base + tid;
        float inv = rsqrtf(bn_var[o] + 1e-5f);
        float scv = bn_gamma[o] * inv;
        sm.scArr[tid] = scv;
        float cb = g_b[o] + g_b[64 + o] + g_b[128 + o];
        sm.shArr[tid] = (cb - bn_mean[o]) * scv + bn_beta[o];
    }

    // ---- load x chunk + M chunk ----
    const float* xg = x + (n * 64 * T_ + t0) * V_;
    for (int idx = tid; idx < 64 * (COLSB / 4); idx += NTB) {
        int c = idx / (COLSB / 4), q = idx % (COLSB / 4);
        float4 val = *reinterpret_cast<const float4*>(xg + c * (T_ * V_) + q * 4);
        *reinterpret_cast<float4*>(&sm.xs[c][q * 4]) = val;
    }
    for (int idx = tid; idx < NS_ * (COLSB / 4); idx += NTB) {
        int s = idx / (COLSB / 4), q = idx % (COLSB / 4);
        float4 val = *reinterpret_cast<const float4*>(
            &g_M[(s * N_ + n) * (T_ * V_) + t0 * V_ + q * 4]);
        *reinterpret_cast<float4*>(&sm.Msm[s][q * 4]) = val;
    }
    __syncthreads();

    // ---- mainloop: 8 rows (4 o-pairs) x 4 cols per thread, fused s ----
    const int rg   = tid / 75;     // 0..3 -> o0 local = rg*8
    const int cg   = tid % 75;     // 0..74
    const int col0 = cg * 4;
    const int o0   = rg * 8;

    float ms[NS_][4];
    #pragma unroll
    for (int s = 0; s < NS_; s++)
        #pragma unroll
        for (int j = 0; j < 4; j++) ms[s][j] = sm.Msm[s][col0 + j];

    ull acc2[4][4];   // [o-pair][col]
    #pragma unroll
    for (int k = 0; k < 4; k++)
        #pragma unroll
        for (int j = 0; j < 4; j++) acc2[k][j] = 0ull;

    #pragma unroll 2
    for (int c = 0; c < 64; c++) {
        float4 xv = *reinterpret_cast<const float4*>(&sm.xs[c][col0]);
        float xa[4] = {xv.x, xv.y, xv.z, xv.w};
        #pragma unroll
        for (int s = 0; s < NS_; s++) {
            const ulonglong2* gp =
                reinterpret_cast<const ulonglong2*>(&sm.GTh[s][c][o0]);
            ulonglong2 g01 = gp[0];   // rows (o0,o0+1),(o0+2,o0+3)
            ulonglong2 g23 = gp[1];   // rows (o0+4,o0+5),(o0+6,o0+7)
            ull xm[4];
            #pragma unroll
            for (int j = 0; j < 4; j++) xm[j] = dup2(xa[j] * ms[s][j]);
            #pragma unroll
            for (int j = 0; j < 4; j++) {
                fma2(acc2[0][j], g01.x, xm[j]);
                fma2(acc2[1][j], g01.y, xm[j]);
                fma2(acc2[2][j], g23.x, xm[j]);
                fma2(acc2[3][j], g23.y, xm[j]);
            }
        }
    }

    // ---- epilogue: BN + residual + ReLU, float4 stores ----
    #pragma unroll
    for (int k = 0; k < 4; k++) {
        int oa = o0 + 2 * k;       // local
        int ob = oa + 1;
        float scA = sm.scArr[oa], shA = sm.shArr[oa];
        float scB = sm.scArr[ob], shB = sm.shArr[ob];
        float ra[4], rb[4];
        #pragma unroll
        for (int j = 0; j < 4; j++) unpack2(acc2[k][j], ra[j], rb[j]);
        float4 xrA = *reinterpret_cast<const float4*>(&sm.xs[o_base + oa][col0]);
        float4 xrB = *reinterpret_cast<const float4*>(&sm.xs[o_base + ob][col0]);
        float4 resA, resB;
        resA.x = fmaxf(ra[0] * scA + shA + xrA.x, 0.f);
        resA.y = fmaxf(ra[1] * scA + shA + xrA.y, 0.f);
        resA.z = fmaxf(ra[2] * scA + shA + xrA.z, 0.f);
        resA.w = fmaxf(ra[3] * scA + shA + xrA.w, 0.f);
        resB.x = fmaxf(rb[0] * scB + shB + xrB.x, 0.f);
        resB.y = fmaxf(rb[1] * scB + shB + xrB.y, 0.f);
        resB.z = fmaxf(rb[2] * scB + shB + xrB.z, 0.f);
        resB.w = fmaxf(rb[3] * scB + shB + xrB.w, 0.f);
        float* opA = out + (n * 64 + o_base + oa) * (T_ * V_) + t0 * V_ + col0;
        float* opB = out + (n * 64 + o_base + ob) * (T_ * V_) + t0 * V_ + col0;
        *reinterpret_cast<float4*>(opA) = resA;
        *reinterpret_cast<float4*>(opB) = resB;
    }
}

extern "C" void kernel_launch(void* const* d_in, const int* in_sizes, int n_in,
                              void* d_out, int out_size)
{
    const float* x        = (const float*)d_in[0];
    const float* A        = (const float*)d_in[1];
    const float* GA       = (const float*)d_in[2];
    const float* g_w      = (const float*)d_in[3];
    const float* g_b      = (const float*)d_in[4];
    const float* a_w      = (const float*)d_in[5];
    const float* a_b      = (const float*)d_in[6];
    const float* b_w      = (const float*)d_in[7];
    const float* b_b      = (const float*)d_in[8];
    const float* bn_gamma = (const float*)d_in[9];
    const float* bn_beta  = (const float*)d_in[10];
    const float* bn_mean  = (const float*)d_in[11];
    const float* bn_var   = (const float*)d_in[12];
    float* out = (float*)d_out;

    size_t smemA = sizeof(SmemA);
    size_t smemB = sizeof(SmemB);
    cudaFuncSetAttribute(tsagc_attn_kernel,
                         cudaFuncAttributeMaxDynamicSharedMemorySize, (int)smemA);
    cudaFuncSetAttribute(tsagc_out_kernel,
                         cudaFuncAttributeMaxDynamicSharedMemorySize, (int)smemB);

    tsagc_attn_kernel<<<GRIDA, NTA, smemA>>>(x, A, GA, a_w, a_b, b_w, b_b);
    tsagc_out_kernel<<<GRIDB, NTB, smemB>>>(x, g_w, g_b, bn_gamma, bn_beta,
                                            bn_mean, bn_var, out);
}